// round 6
// baseline (speedup 1.0000x reference)
#include <cuda_runtime.h>
#include <math.h>

#define NB 2
#define NT 2048
#define ND 1024
#define NH 16
#define NM (NB * NT)   // 4096 rows

// Scratch (allocation-free: __device__ globals)
__device__ __align__(16) float g_qT[NB * ND * NT];   // [b][n][t] d-major, RoPE'd
__device__ __align__(16) float g_kT[NB * ND * NT];   // [b][n][t] d-major, RoPE'd
__device__ __align__(16) float g_v [NM * ND];        // [m][n] natural
__device__ __align__(16) float g_xo[NM * ND];        // attention output, natural
__device__ __align__(16) float g_rope[NT * 64];      // [t][pair]{cos,sin}

// ---------------------------------------------------------------------------
// RoPE cos/sin table: pair index ip in [0,32), angle = t * 10000^(-2*ip/64)
// freq computed in double so the fp32-rounded freq matches the reference.
// ---------------------------------------------------------------------------
__global__ void rope_fill_kernel()
{
    int id = blockIdx.x * 256 + threadIdx.x;
    if (id >= NT * 32) return;
    int t  = id >> 5;
    int ip = id & 31;
    float freq = (float)exp((double)(2 * ip) * -0.14391156831212787); // -ln(10000)/64
    float ang  = (float)t * freq;
    float s, c;
    sincosf(ang, &s, &c);
    g_rope[2 * id + 0] = c;
    g_rope[2 * id + 1] = s;
}

// ---------------------------------------------------------------------------
// C[m,n] = sum_k A[m,k] * W[n,k]   (M=4096, N=1024, K=1024)
// mode 0: C -> g_qT (transposed d-major) with fused RoPE
// mode 1: C -> g_kT (transposed d-major) with fused RoPE
// mode 2: C -> g_v  (natural)
// mode 3: A  = g_xo, C -> Cext (natural, final output)
// 128x128x16 tile, 256 threads, 8x8 per thread, register prefetch.
// ---------------------------------------------------------------------------
template <bool QKV>
__device__ __forceinline__
void gemm128_body(const float* __restrict__ A, const float* __restrict__ W,
                  float* __restrict__ C, int mode)
{
    __shared__ __align__(16) float As[16][132];
    __shared__ __align__(16) float Bs[16][132];

    const int tid = threadIdx.x;
    const int tx  = tid & 15;
    const int ty  = tid >> 4;
    const int bn0 = blockIdx.x * 128;
    const int bm0 = blockIdx.y * 128;

    const float* Ab = A + (size_t)bm0 * ND;
    const float* Wb = W + (size_t)bn0 * ND;

    const int ar0 = tid >> 2;          // 0..63
    const int ar1 = ar0 + 64;          // 64..127
    const int akc = (tid & 3) << 2;    // 0,4,8,12

    // prefetch first k-tile
    float4 pa0 = *(const float4*)(Ab + (size_t)ar0 * ND + akc);
    float4 pa1 = *(const float4*)(Ab + (size_t)ar1 * ND + akc);
    float4 pb0 = *(const float4*)(Wb + (size_t)ar0 * ND + akc);
    float4 pb1 = *(const float4*)(Wb + (size_t)ar1 * ND + akc);

    float acc[8][8];
    #pragma unroll
    for (int i = 0; i < 8; ++i)
        #pragma unroll
        for (int j = 0; j < 8; ++j) acc[i][j] = 0.0f;

    for (int k0 = 0; k0 < ND; k0 += 16) {
        // commit prefetched tile to smem (transposed k-major)
        As[akc + 0][ar0] = pa0.x; As[akc + 1][ar0] = pa0.y;
        As[akc + 2][ar0] = pa0.z; As[akc + 3][ar0] = pa0.w;
        As[akc + 0][ar1] = pa1.x; As[akc + 1][ar1] = pa1.y;
        As[akc + 2][ar1] = pa1.z; As[akc + 3][ar1] = pa1.w;
        Bs[akc + 0][ar0] = pb0.x; Bs[akc + 1][ar0] = pb0.y;
        Bs[akc + 2][ar0] = pb0.z; Bs[akc + 3][ar0] = pb0.w;
        Bs[akc + 0][ar1] = pb1.x; Bs[akc + 1][ar1] = pb1.y;
        Bs[akc + 2][ar1] = pb1.z; Bs[akc + 3][ar1] = pb1.w;
        __syncthreads();

        if (k0 + 16 < ND) {  // issue next tile's loads; land during compute
            const float* An = Ab + (k0 + 16 + akc);
            pa0 = *(const float4*)(An + (size_t)ar0 * ND);
            pa1 = *(const float4*)(An + (size_t)ar1 * ND);
            const float* Wn = Wb + (k0 + 16 + akc);
            pb0 = *(const float4*)(Wn + (size_t)ar0 * ND);
            pb1 = *(const float4*)(Wn + (size_t)ar1 * ND);
        }

        #pragma unroll 4
        for (int kk = 0; kk < 16; ++kk) {
            float4 a0v = *(const float4*)&As[kk][ty * 8];
            float4 a1v = *(const float4*)&As[kk][ty * 8 + 4];
            float4 b0v = *(const float4*)&Bs[kk][tx * 8];
            float4 b1v = *(const float4*)&Bs[kk][tx * 8 + 4];
            float a[8] = {a0v.x, a0v.y, a0v.z, a0v.w, a1v.x, a1v.y, a1v.z, a1v.w};
            float b[8] = {b0v.x, b0v.y, b0v.z, b0v.w, b1v.x, b1v.y, b1v.z, b1v.w};
            #pragma unroll
            for (int i = 0; i < 8; ++i)
                #pragma unroll
                for (int j = 0; j < 8; ++j)
                    acc[i][j] = fmaf(a[i], b[j], acc[i][j]);
        }
        __syncthreads();
    }

    if (!QKV || mode >= 2) {
        // natural [m][n] store
        #pragma unroll
        for (int i = 0; i < 8; ++i) {
            size_t m = (size_t)(bm0 + ty * 8 + i);
            float* cp = C + m * ND + bn0 + tx * 8;
            *(float4*)cp       = make_float4(acc[i][0], acc[i][1], acc[i][2], acc[i][3]);
            *(float4*)(cp + 4) = make_float4(acc[i][4], acc[i][5], acc[i][6], acc[i][7]);
        }
    } else {
        // fused RoPE + transposed store: addr = b*2^21 + n*2048 + t
        const int nbase = bn0 + tx * 8;             // 8 consecutive n = 4 RoPE pairs
        const int ip0   = (nbase & 63) >> 1;        // pair index within head
        #pragma unroll
        for (int i = 0; i < 8; ++i) {
            int m  = bm0 + ty * 8 + i;
            int bb = m >> 11;
            int t  = m & (NT - 1);
            const float4* rp = (const float4*)&g_rope[t * 64 + ip0 * 2];
            float4 r01 = rp[0];
            float4 r23 = rp[1];
            float* cb = C + (size_t)bb * (ND * NT) + t;
            cb[(size_t)(nbase + 0) * NT] = acc[i][0] * r01.x - acc[i][1] * r01.y;
            cb[(size_t)(nbase + 1) * NT] = acc[i][0] * r01.y + acc[i][1] * r01.x;
            cb[(size_t)(nbase + 2) * NT] = acc[i][2] * r01.z - acc[i][3] * r01.w;
            cb[(size_t)(nbase + 3) * NT] = acc[i][2] * r01.w + acc[i][3] * r01.z;
            cb[(size_t)(nbase + 4) * NT] = acc[i][4] * r23.x - acc[i][5] * r23.y;
            cb[(size_t)(nbase + 5) * NT] = acc[i][4] * r23.y + acc[i][5] * r23.x;
            cb[(size_t)(nbase + 6) * NT] = acc[i][6] * r23.z - acc[i][7] * r23.w;
            cb[(size_t)(nbase + 7) * NT] = acc[i][6] * r23.w + acc[i][7] * r23.z;
        }
    }
}

// Fused Q/K/V projection: blockIdx.z selects weight + epilogue mode.
__global__ __launch_bounds__(256, 2)
void gemm_qkv_kernel(const float* __restrict__ x,
                     const float* __restrict__ wq,
                     const float* __restrict__ wk,
                     const float* __restrict__ wv)
{
    const int mode = blockIdx.z;                    // 0=Q, 1=K, 2=V
    const float* W = (mode == 0) ? wq : (mode == 1) ? wk : wv;
    float* C = (mode == 0) ? g_qT : (mode == 1) ? g_kT : g_v;
    gemm128_body<true>(x, W, C, mode);
}

// Output projection: A = g_xo, C = harness output buffer.
__global__ __launch_bounds__(256, 2)
void gemm_out_kernel(const float* __restrict__ wo, float* __restrict__ out)
{
    gemm128_body<false>(g_xo, wo, out, 3);
}

// ---------------------------------------------------------------------------
// Causal flash attention. grid = (32 q-tiles, 32 (b,h)), 256 threads.
// 64x64 tiles, head_dim 64. Q/K read d-major (no transpose needed).
// Static shared: 3 x 64x64 fp32 tiles = 49152 B exactly (no opt-in needed).
// Thread (tx,ty) owns S rows ty*4.. cols tx*4..; row reductions via shfl-xor
// within the 16-lane tx group. P transposed through smem (reusing K buffer)
// for the PV pass. Output normalized and written to g_xo [m][n].
// ---------------------------------------------------------------------------
__global__ __launch_bounds__(256)
void attn_kernel()
{
    __shared__ __align__(16) float Qt[64 * 64];  // Qt[d][r]
    __shared__ __align__(16) float KP[64 * 64];  // K[d][c], later P^T[c][r]
    __shared__ __align__(16) float Vs[64 * 64];  // V[c][dd]

    const int tid = threadIdx.x;
    const int tx  = tid & 15;
    const int ty  = tid >> 4;
    const int qt  = blockIdx.x;      // 0..31
    const int bh  = blockIdx.y;      // 0..31
    const int b   = bh >> 4;
    const int h   = bh & 15;
    const int qb  = qt * 64;

    const size_t tbase = (size_t)b * (ND * NT) + (size_t)(h * 64) * NT;  // + d*NT + t
    const size_t vbase = (size_t)(b * NT) * ND + h * 64;

    // load Q tile (d-major, coalesced along t)
    #pragma unroll
    for (int u = 0; u < 4; ++u) {
        int fi = tid + (u << 8);
        int d  = fi >> 4;
        int r4 = (fi & 15) << 2;
        *(float4*)&Qt[d * 64 + r4] =
            *(const float4*)&g_qT[tbase + (size_t)d * NT + qb + r4];
    }

    float m_i[4], l_i[4], o[4][4];
    #pragma unroll
    for (int i = 0; i < 4; ++i) {
        m_i[i] = -3.0e38f;
        l_i[i] = 0.0f;
        #pragma unroll
        for (int j = 0; j < 4; ++j) o[i][j] = 0.0f;
    }

    for (int kt = 0; kt <= qt; ++kt) {
        const int kb = kt * 64;
        __syncthreads();  // previous PV pass done reading KP/Vs (and Q visible on kt=0)
        #pragma unroll
        for (int u = 0; u < 4; ++u) {
            int fi = tid + (u << 8);
            int r  = fi >> 4;
            int c4 = (fi & 15) << 2;
            *(float4*)&KP[r * 64 + c4] =
                *(const float4*)&g_kT[tbase + (size_t)r * NT + kb + c4];
            *(float4*)&Vs[r * 64 + c4] =
                *(const float4*)&g_v[vbase + (size_t)(kb + r) * ND + c4];
        }
        __syncthreads();

        // S = Q . K^T  (raw scores; 1/sqrt(64) applied inside exp)
        float s[4][4];
        #pragma unroll
        for (int i = 0; i < 4; ++i)
            #pragma unroll
            for (int j = 0; j < 4; ++j) s[i][j] = 0.0f;

        #pragma unroll 8
        for (int d = 0; d < 64; ++d) {
            float4 av = *(const float4*)&Qt[d * 64 + ty * 4];
            float4 bv = *(const float4*)&KP[d * 64 + tx * 4];
            float ar[4] = {av.x, av.y, av.z, av.w};
            float br[4] = {bv.x, bv.y, bv.z, bv.w};
            #pragma unroll
            for (int i = 0; i < 4; ++i)
                #pragma unroll
                for (int j = 0; j < 4; ++j)
                    s[i][j] = fmaf(ar[i], br[j], s[i][j]);
        }

        if (kt == qt) {  // diagonal tile: causal mask (kb == qb)
            #pragma unroll
            for (int i = 0; i < 4; ++i)
                #pragma unroll
                for (int j = 0; j < 4; ++j)
                    if (tx * 4 + j > ty * 4 + i) s[i][j] = -1.0e30f;
        }

        // online softmax update
        #pragma unroll
        for (int i = 0; i < 4; ++i) {
            float mx = fmaxf(fmaxf(s[i][0], s[i][1]), fmaxf(s[i][2], s[i][3]));
            mx = fmaxf(mx, __shfl_xor_sync(0xffffffffu, mx, 1));
            mx = fmaxf(mx, __shfl_xor_sync(0xffffffffu, mx, 2));
            mx = fmaxf(mx, __shfl_xor_sync(0xffffffffu, mx, 4));
            mx = fmaxf(mx, __shfl_xor_sync(0xffffffffu, mx, 8));
            float mn = fmaxf(m_i[i], mx);
            float al = __expf((m_i[i] - mn) * 0.125f);
            m_i[i] = mn;
            float ps = 0.0f;
            #pragma unroll
            for (int j = 0; j < 4; ++j) {
                s[i][j] = __expf((s[i][j] - mn) * 0.125f);
                ps += s[i][j];
            }
            ps += __shfl_xor_sync(0xffffffffu, ps, 1);
            ps += __shfl_xor_sync(0xffffffffu, ps, 2);
            ps += __shfl_xor_sync(0xffffffffu, ps, 4);
            ps += __shfl_xor_sync(0xffffffffu, ps, 8);
            l_i[i] = l_i[i] * al + ps;
            #pragma unroll
            for (int j = 0; j < 4; ++j) o[i][j] *= al;
        }

        __syncthreads();  // all S reads of KP done
        // write P^T into KP: P^T[c][r]
        #pragma unroll
        for (int j = 0; j < 4; ++j)
            #pragma unroll
            for (int i = 0; i < 4; ++i)
                KP[(tx * 4 + j) * 64 + ty * 4 + i] = s[i][j];
        __syncthreads();

        // O += P . V
        #pragma unroll 8
        for (int c = 0; c < 64; ++c) {
            float4 av = *(const float4*)&KP[c * 64 + ty * 4];
            float4 bv = *(const float4*)&Vs[c * 64 + tx * 4];
            float ar[4] = {av.x, av.y, av.z, av.w};
            float br[4] = {bv.x, bv.y, bv.z, bv.w};
            #pragma unroll
            for (int i = 0; i < 4; ++i)
                #pragma unroll
                for (int j = 0; j < 4; ++j)
                    o[i][j] = fmaf(ar[i], br[j], o[i][j]);
        }
    }

    // normalize and store (natural layout for final projection)
    #pragma unroll
    for (int i = 0; i < 4; ++i) {
        float inv = 1.0f / l_i[i];
        int t = qb + ty * 4 + i;
        float4 v = make_float4(o[i][0] * inv, o[i][1] * inv,
                               o[i][2] * inv, o[i][3] * inv);
        *(float4*)&g_xo[(size_t)(b * NT + t) * ND + h * 64 + tx * 4] = v;
    }
}

// ---------------------------------------------------------------------------
extern "C" void kernel_launch(void* const* d_in, const int* in_sizes, int n_in,
                              void* d_out, int out_size)
{
    const float* x  = (const float*)d_in[0];
    const float* wq = (const float*)d_in[1];
    const float* wk = (const float*)d_in[2];
    const float* wv = (const float*)d_in[3];
    const float* wo = (const float*)d_in[4];
    float* out = (float*)d_out;

    rope_fill_kernel<<<(NT * 32 + 255) / 256, 256>>>();

    dim3 gqkv(ND / 128, NM / 128, 3);                 // (8, 32, 3)
    gemm_qkv_kernel<<<gqkv, 256>>>(x, wq, wk, wv);    // Q/K/V proj (+RoPE on Q/K)

    attn_kernel<<<dim3(32, 32), 256>>>();             // causal flash attention

    dim3 go(ND / 128, NM / 128);                      // (8, 32)
    gemm_out_kernel<<<go, 256>>>(wo, out);            // output projection
}

// round 8
// speedup vs baseline: 1.0897x; 1.0897x over previous
#include <cuda_runtime.h>
#include <math.h>

#define NB 2
#define NT 2048
#define ND 1024
#define NH 16
#define NM (NB * NT)   // 4096 rows

typedef unsigned long long u64;

// Scratch (allocation-free: __device__ globals)
__device__ __align__(16) float g_qT[NB * ND * NT];   // [b][n][t] d-major, RoPE'd
__device__ __align__(16) float g_kT[NB * ND * NT];   // [b][n][t] d-major, RoPE'd
__device__ __align__(16) float g_v [NM * ND];        // [m][n] natural
__device__ __align__(16) float g_xo[NM * ND];        // attention output, natural
__device__ __align__(16) float g_rope[NT * 64];      // [t][pair]{cos,sin}

// ---- packed f32x2 helpers (Blackwell FFMA2 path; ptxas never auto-fuses) ----
__device__ __forceinline__ u64 pk2(float x, float y)
{
    u64 r; asm("mov.b64 %0, {%1, %2};" : "=l"(r) : "f"(x), "f"(y)); return r;
}
__device__ __forceinline__ void upk2(u64 v, float& x, float& y)
{
    asm("mov.b64 {%0, %1}, %2;" : "=f"(x), "=f"(y) : "l"(v));
}
__device__ __forceinline__ void fma2(u64& d, u64 a, u64 b)
{
    asm("fma.rn.f32x2 %0, %1, %2, %0;" : "+l"(d) : "l"(a), "l"(b));
}
__device__ __forceinline__ void mul2(u64& d, u64 a)
{
    asm("mul.rn.f32x2 %0, %0, %1;" : "+l"(d) : "l"(a));
}

// ---------------------------------------------------------------------------
// RoPE cos/sin table: pair index ip in [0,32), angle = t * 10000^(-2*ip/64)
// freq computed in double so the fp32-rounded freq matches the reference.
// ---------------------------------------------------------------------------
__global__ void rope_fill_kernel()
{
    int id = blockIdx.x * 256 + threadIdx.x;
    if (id >= NT * 32) return;
    int t  = id >> 5;
    int ip = id & 31;
    float freq = (float)exp((double)(2 * ip) * -0.14391156831212787); // -ln(10000)/64
    float ang  = (float)t * freq;
    float s, c;
    sincosf(ang, &s, &c);
    g_rope[2 * id + 0] = c;
    g_rope[2 * id + 1] = s;
}

// ---------------------------------------------------------------------------
// C[m,n] = sum_k A[m,k] * W[n,k]   (M=4096, N=1024, K=1024)
// 128x128x16 tile, 256 threads, 8x8 per thread, packed f32x2 accumulators
// (8 rows x 4 j-pairs), register prefetch double buffering.
// mode 0/1: C -> g_qT/g_kT transposed d-major with fused RoPE
// mode 2:   C -> g_v natural; mode 3: A=g_xo, C natural (final output)
// ---------------------------------------------------------------------------
template <bool QKV>
__device__ __forceinline__
void gemm128_body(const float* __restrict__ A, const float* __restrict__ W,
                  float* __restrict__ C, int mode)
{
    __shared__ __align__(16) float As[16][132];
    __shared__ __align__(16) float Bs[16][132];

    const int tid = threadIdx.x;
    const int tx  = tid & 15;
    const int ty  = tid >> 4;
    const int bn0 = blockIdx.x * 128;
    const int bm0 = blockIdx.y * 128;

    const float* Ab = A + (size_t)bm0 * ND;
    const float* Wb = W + (size_t)bn0 * ND;

    const int ar0 = tid >> 2;          // 0..63
    const int ar1 = ar0 + 64;          // 64..127
    const int akc = (tid & 3) << 2;    // 0,4,8,12

    // prefetch first k-tile
    float4 pa0 = *(const float4*)(Ab + (size_t)ar0 * ND + akc);
    float4 pa1 = *(const float4*)(Ab + (size_t)ar1 * ND + akc);
    float4 pb0 = *(const float4*)(Wb + (size_t)ar0 * ND + akc);
    float4 pb1 = *(const float4*)(Wb + (size_t)ar1 * ND + akc);

    u64 acc[8][4];                     // [row][j-pair] packed (j even, j odd)
    #pragma unroll
    for (int i = 0; i < 8; ++i)
        #pragma unroll
        for (int j = 0; j < 4; ++j) acc[i][j] = 0ULL;

    for (int k0 = 0; k0 < ND; k0 += 16) {
        // commit prefetched tile to smem (transposed k-major)
        As[akc + 0][ar0] = pa0.x; As[akc + 1][ar0] = pa0.y;
        As[akc + 2][ar0] = pa0.z; As[akc + 3][ar0] = pa0.w;
        As[akc + 0][ar1] = pa1.x; As[akc + 1][ar1] = pa1.y;
        As[akc + 2][ar1] = pa1.z; As[akc + 3][ar1] = pa1.w;
        Bs[akc + 0][ar0] = pb0.x; Bs[akc + 1][ar0] = pb0.y;
        Bs[akc + 2][ar0] = pb0.z; Bs[akc + 3][ar0] = pb0.w;
        Bs[akc + 0][ar1] = pb1.x; Bs[akc + 1][ar1] = pb1.y;
        Bs[akc + 2][ar1] = pb1.z; Bs[akc + 3][ar1] = pb1.w;
        __syncthreads();

        if (k0 + 16 < ND) {  // issue next tile's loads; land during compute
            const float* An = Ab + (k0 + 16 + akc);
            pa0 = *(const float4*)(An + (size_t)ar0 * ND);
            pa1 = *(const float4*)(An + (size_t)ar1 * ND);
            const float* Wn = Wb + (k0 + 16 + akc);
            pb0 = *(const float4*)(Wn + (size_t)ar0 * ND);
            pb1 = *(const float4*)(Wn + (size_t)ar1 * ND);
        }

        #pragma unroll 4
        for (int kk = 0; kk < 16; ++kk) {
            float4 a0v = *(const float4*)&As[kk][ty * 8];
            float4 a1v = *(const float4*)&As[kk][ty * 8 + 4];
            ulonglong2 b01 = *(const ulonglong2*)&Bs[kk][tx * 8];
            ulonglong2 b23 = *(const ulonglong2*)&Bs[kk][tx * 8 + 4];
            u64 bb[4] = {b01.x, b01.y, b23.x, b23.y};
            float af[8] = {a0v.x, a0v.y, a0v.z, a0v.w,
                           a1v.x, a1v.y, a1v.z, a1v.w};
            #pragma unroll
            for (int i = 0; i < 8; ++i) {
                u64 ad = pk2(af[i], af[i]);
                #pragma unroll
                for (int j = 0; j < 4; ++j)
                    fma2(acc[i][j], ad, bb[j]);
            }
        }
        __syncthreads();
    }

    if (!QKV || mode >= 2) {
        // natural [m][n] store
        #pragma unroll
        for (int i = 0; i < 8; ++i) {
            float r[8];
            #pragma unroll
            for (int j = 0; j < 4; ++j) upk2(acc[i][j], r[2 * j], r[2 * j + 1]);
            size_t m = (size_t)(bm0 + ty * 8 + i);
            float* cp = C + m * ND + bn0 + tx * 8;
            *(float4*)cp       = make_float4(r[0], r[1], r[2], r[3]);
            *(float4*)(cp + 4) = make_float4(r[4], r[5], r[6], r[7]);
        }
    } else {
        // fused RoPE + transposed store: addr = b*2^21 + n*2048 + t
        const int nbase = bn0 + tx * 8;             // 8 consecutive n = 4 RoPE pairs
        const int ip0   = (nbase & 63) >> 1;        // pair index within head
        #pragma unroll
        for (int i = 0; i < 8; ++i) {
            float r[8];
            #pragma unroll
            for (int j = 0; j < 4; ++j) upk2(acc[i][j], r[2 * j], r[2 * j + 1]);
            int m  = bm0 + ty * 8 + i;
            int bb = m >> 11;
            int t  = m & (NT - 1);
            const float4* rp = (const float4*)&g_rope[t * 64 + ip0 * 2];
            float4 r01 = rp[0];
            float4 r23 = rp[1];
            float* cb = C + (size_t)bb * (ND * NT) + t;
            cb[(size_t)(nbase + 0) * NT] = r[0] * r01.x - r[1] * r01.y;
            cb[(size_t)(nbase + 1) * NT] = r[0] * r01.y + r[1] * r01.x;
            cb[(size_t)(nbase + 2) * NT] = r[2] * r01.z - r[3] * r01.w;
            cb[(size_t)(nbase + 3) * NT] = r[2] * r01.w + r[3] * r01.z;
            cb[(size_t)(nbase + 4) * NT] = r[4] * r23.x - r[5] * r23.y;
            cb[(size_t)(nbase + 5) * NT] = r[4] * r23.y + r[5] * r23.x;
            cb[(size_t)(nbase + 6) * NT] = r[6] * r23.z - r[7] * r23.w;
            cb[(size_t)(nbase + 7) * NT] = r[6] * r23.w + r[7] * r23.z;
        }
    }
}

// Fused Q/K/V projection: blockIdx.z selects weight + epilogue mode.
__global__ __launch_bounds__(256, 2)
void gemm_qkv_kernel(const float* __restrict__ x,
                     const float* __restrict__ wq,
                     const float* __restrict__ wk,
                     const float* __restrict__ wv)
{
    const int mode = blockIdx.z;                    // 0=Q, 1=K, 2=V
    const float* W = (mode == 0) ? wq : (mode == 1) ? wk : wv;
    float* C = (mode == 0) ? g_qT : (mode == 1) ? g_kT : g_v;
    gemm128_body<true>(x, W, C, mode);
}

// Output projection: A = g_xo, C = harness output buffer.
__global__ __launch_bounds__(256, 2)
void gemm_out_kernel(const float* __restrict__ wo, float* __restrict__ out)
{
    gemm128_body<false>(g_xo, wo, out, 3);
}

// ---------------------------------------------------------------------------
// Causal flash attention. grid = (32 q-tiles, 32 (b,h)), 256 threads.
// 64x64 tiles, head_dim 64. Q/K read d-major (no transpose needed).
// Static shared: 3 x 64x64 fp32 tiles = 49152 B exactly.
// Thread (tx,ty) owns S rows ty*4.. cols tx*4.. with packed-f32x2 j-pairs;
// row reductions via shfl-xor within the 16-lane tx group. P transposed
// through smem (reusing K buffer) for the PV pass. Heavy q-tiles launch
// first (qt reversed) to shrink the triangular-workload tail.
// ---------------------------------------------------------------------------
__global__ __launch_bounds__(256)
void attn_kernel()
{
    __shared__ __align__(16) float Qt[64 * 64];  // Qt[d][r]
    __shared__ __align__(16) float KP[64 * 64];  // K[d][c], later P^T[c][r]
    __shared__ __align__(16) float Vs[64 * 64];  // V[c][dd]

    const int tid = threadIdx.x;
    const int tx  = tid & 15;
    const int ty  = tid >> 4;
    const int qt  = 31 - blockIdx.x; // heavy tiles first
    const int bh  = blockIdx.y;      // 0..31
    const int b   = bh >> 4;
    const int h   = bh & 15;
    const int qb  = qt * 64;

    const size_t tbase = (size_t)b * (ND * NT) + (size_t)(h * 64) * NT;  // + d*NT + t
    const size_t vbase = (size_t)(b * NT) * ND + h * 64;

    // load Q tile (d-major, coalesced along t)
    #pragma unroll
    for (int u = 0; u < 4; ++u) {
        int fi = tid + (u << 8);
        int d  = fi >> 4;
        int r4 = (fi & 15) << 2;
        *(float4*)&Qt[d * 64 + r4] =
            *(const float4*)&g_qT[tbase + (size_t)d * NT + qb + r4];
    }

    float m_i[4], l_i[4];
    u64   o[4][2];                   // packed j-pairs
    #pragma unroll
    for (int i = 0; i < 4; ++i) {
        m_i[i] = -3.0e38f;
        l_i[i] = 0.0f;
        o[i][0] = 0ULL; o[i][1] = 0ULL;
    }

    for (int kt = 0; kt <= qt; ++kt) {
        const int kb = kt * 64;
        __syncthreads();  // previous PV pass done reading KP/Vs (and Q visible on kt=0)
        #pragma unroll
        for (int u = 0; u < 4; ++u) {
            int fi = tid + (u << 8);
            int r  = fi >> 4;
            int c4 = (fi & 15) << 2;
            *(float4*)&KP[r * 64 + c4] =
                *(const float4*)&g_kT[tbase + (size_t)r * NT + kb + c4];
            *(float4*)&Vs[r * 64 + c4] =
                *(const float4*)&g_v[vbase + (size_t)(kb + r) * ND + c4];
        }
        __syncthreads();

        // S = Q . K^T (packed over j; raw scores, 1/8 applied inside exp)
        u64 sp[4][2];
        #pragma unroll
        for (int i = 0; i < 4; ++i) { sp[i][0] = 0ULL; sp[i][1] = 0ULL; }

        #pragma unroll 8
        for (int d = 0; d < 64; ++d) {
            float4 av = *(const float4*)&Qt[d * 64 + ty * 4];
            ulonglong2 bp = *(const ulonglong2*)&KP[d * 64 + tx * 4];
            float ar[4] = {av.x, av.y, av.z, av.w};
            #pragma unroll
            for (int i = 0; i < 4; ++i) {
                u64 ad = pk2(ar[i], ar[i]);
                fma2(sp[i][0], ad, bp.x);
                fma2(sp[i][1], ad, bp.y);
            }
        }

        float s[4][4];
        #pragma unroll
        for (int i = 0; i < 4; ++i) {
            upk2(sp[i][0], s[i][0], s[i][1]);
            upk2(sp[i][1], s[i][2], s[i][3]);
        }

        if (kt == qt) {  // diagonal tile: causal mask (kb == qb)
            #pragma unroll
            for (int i = 0; i < 4; ++i)
                #pragma unroll
                for (int j = 0; j < 4; ++j)
                    if (tx * 4 + j > ty * 4 + i) s[i][j] = -1.0e30f;
        }

        // online softmax update
        #pragma unroll
        for (int i = 0; i < 4; ++i) {
            float mx = fmaxf(fmaxf(s[i][0], s[i][1]), fmaxf(s[i][2], s[i][3]));
            mx = fmaxf(mx, __shfl_xor_sync(0xffffffffu, mx, 1));
            mx = fmaxf(mx, __shfl_xor_sync(0xffffffffu, mx, 2));
            mx = fmaxf(mx, __shfl_xor_sync(0xffffffffu, mx, 4));
            mx = fmaxf(mx, __shfl_xor_sync(0xffffffffu, mx, 8));
            float mn = fmaxf(m_i[i], mx);
            float al = __expf((m_i[i] - mn) * 0.125f);
            m_i[i] = mn;
            float ps = 0.0f;
            #pragma unroll
            for (int j = 0; j < 4; ++j) {
                s[i][j] = __expf((s[i][j] - mn) * 0.125f);
                ps += s[i][j];
            }
            ps += __shfl_xor_sync(0xffffffffu, ps, 1);
            ps += __shfl_xor_sync(0xffffffffu, ps, 2);
            ps += __shfl_xor_sync(0xffffffffu, ps, 4);
            ps += __shfl_xor_sync(0xffffffffu, ps, 8);
            l_i[i] = l_i[i] * al + ps;
            u64 alp = pk2(al, al);
            mul2(o[i][0], alp);
            mul2(o[i][1], alp);
        }

        __syncthreads();  // all S reads of KP done
        // write P^T into KP: P^T[c][r]
        #pragma unroll
        for (int j = 0; j < 4; ++j)
            #pragma unroll
            for (int i = 0; i < 4; ++i)
                KP[(tx * 4 + j) * 64 + ty * 4 + i] = s[i][j];
        __syncthreads();

        // O += P . V (packed over j)
        #pragma unroll 8
        for (int c = 0; c < 64; ++c) {
            float4 av = *(const float4*)&KP[c * 64 + ty * 4];
            ulonglong2 bp = *(const ulonglong2*)&Vs[c * 64 + tx * 4];
            float ar[4] = {av.x, av.y, av.z, av.w};
            #pragma unroll
            for (int i = 0; i < 4; ++i) {
                u64 ad = pk2(ar[i], ar[i]);
                fma2(o[i][0], ad, bp.x);
                fma2(o[i][1], ad, bp.y);
            }
        }
    }

    // normalize and store (natural layout for final projection)
    #pragma unroll
    for (int i = 0; i < 4; ++i) {
        float inv = 1.0f / l_i[i];
        float r[4];
        upk2(o[i][0], r[0], r[1]);
        upk2(o[i][1], r[2], r[3]);
        int t = qb + ty * 4 + i;
        float4 v = make_float4(r[0] * inv, r[1] * inv, r[2] * inv, r[3] * inv);
        *(float4*)&g_xo[(size_t)(b * NT + t) * ND + h * 64 + tx * 4] = v;
    }
}

// ---------------------------------------------------------------------------
extern "C" void kernel_launch(void* const* d_in, const int* in_sizes, int n_in,
                              void* d_out, int out_size)
{
    const float* x  = (const float*)d_in[0];
    const float* wq = (const float*)d_in[1];
    const float* wk = (const float*)d_in[2];
    const float* wv = (const float*)d_in[3];
    const float* wo = (const float*)d_in[4];
    float* out = (float*)d_out;

    rope_fill_kernel<<<(NT * 32 + 255) / 256, 256>>>();

    dim3 gqkv(ND / 128, NM / 128, 3);                 // (8, 32, 3)
    gemm_qkv_kernel<<<gqkv, 256>>>(x, wq, wk, wv);    // Q/K/V proj (+RoPE on Q/K)

    attn_kernel<<<dim3(32, 32), 256>>>();             // causal flash attention

    dim3 go(ND / 128, NM / 128);                      // (8, 32)
    gemm_out_kernel<<<go, 256>>>(wo, out);            // output projection
}

// round 9
// speedup vs baseline: 1.1010x; 1.0103x over previous
#include <cuda_runtime.h>
#include <math.h>

#define NB 2
#define NT 2048
#define ND 1024
#define NH 16
#define NM (NB * NT)   // 4096 rows

typedef unsigned long long u64;

// Scratch (allocation-free: __device__ globals)
__device__ __align__(16) float g_qT[NB * ND * NT];   // [b][n][t] d-major, RoPE'd
__device__ __align__(16) float g_kT[NB * ND * NT];   // [b][n][t] d-major, RoPE'd
__device__ __align__(16) float g_v [NM * ND];        // [m][n] natural
__device__ __align__(16) float g_xo[NM * ND];        // attention output, natural
__device__ __align__(16) float g_rope[NT * 64];      // [t][pair]{cos,sin}

// ---- packed f32x2 helpers (Blackwell FFMA2 path; ptxas never auto-fuses) ----
__device__ __forceinline__ u64 pk2(float x, float y)
{
    u64 r; asm("mov.b64 %0, {%1, %2};" : "=l"(r) : "f"(x), "f"(y)); return r;
}
__device__ __forceinline__ void upk2(u64 v, float& x, float& y)
{
    asm("mov.b64 {%0, %1}, %2;" : "=f"(x), "=f"(y) : "l"(v));
}
__device__ __forceinline__ void fma2(u64& d, u64 a, u64 b)
{
    asm("fma.rn.f32x2 %0, %1, %2, %0;" : "+l"(d) : "l"(a), "l"(b));
}
__device__ __forceinline__ void mul2(u64& d, u64 a)
{
    asm("mul.rn.f32x2 %0, %0, %1;" : "+l"(d) : "l"(a));
}

// ---------------------------------------------------------------------------
// RoPE cos/sin table: pair index ip in [0,32), angle = t * 10000^(-2*ip/64)
// ---------------------------------------------------------------------------
__global__ void rope_fill_kernel()
{
    int id = blockIdx.x * 256 + threadIdx.x;
    if (id >= NT * 32) return;
    int t  = id >> 5;
    int ip = id & 31;
    float freq = (float)exp((double)(2 * ip) * -0.14391156831212787); // -ln(10000)/64
    float ang  = (float)t * freq;
    float s, c;
    sincosf(ang, &s, &c);
    g_rope[2 * id + 0] = c;
    g_rope[2 * id + 1] = s;
}

// ---------------------------------------------------------------------------
// C[m,n] = sum_k A[m,k] * W[n,k]   (M=4096, N=1024, K=1024)
// 128x128x16 tile, 256 threads, 8x8 per thread, packed f32x2 accumulators,
// register-prefetch double buffering. Warp tiled 4x8 (4 row-threads x 8
// col-threads) so B smem reads touch 8 distinct 16B chunks (1 wavefront).
// ---------------------------------------------------------------------------
template <bool QKV>
__device__ __forceinline__
void gemm128_body(const float* __restrict__ A, const float* __restrict__ W,
                  float* __restrict__ C, int mode)
{
    __shared__ __align__(16) float As[16][132];
    __shared__ __align__(16) float Bs[16][132];

    const int tid = threadIdx.x;
    const int w   = tid >> 5;
    const int l   = tid & 31;
    const int ri  = (w & 3) * 4 + (l >> 3);   // 0..15 row-thread
    const int ci  = (w >> 2) * 8 + (l & 7);   // 0..15 col-thread
    const int bn0 = blockIdx.x * 128;
    const int bm0 = blockIdx.y * 128;

    const float* Ab = A + (size_t)bm0 * ND;
    const float* Wb = W + (size_t)bn0 * ND;

    const int ar0 = tid >> 2;          // 0..63
    const int ar1 = ar0 + 64;          // 64..127
    const int akc = (tid & 3) << 2;    // 0,4,8,12

    // prefetch first k-tile
    float4 pa0 = *(const float4*)(Ab + (size_t)ar0 * ND + akc);
    float4 pa1 = *(const float4*)(Ab + (size_t)ar1 * ND + akc);
    float4 pb0 = *(const float4*)(Wb + (size_t)ar0 * ND + akc);
    float4 pb1 = *(const float4*)(Wb + (size_t)ar1 * ND + akc);

    u64 acc[8][4];                     // [row][j-pair] packed (j even, j odd)
    #pragma unroll
    for (int i = 0; i < 8; ++i)
        #pragma unroll
        for (int j = 0; j < 4; ++j) acc[i][j] = 0ULL;

    for (int k0 = 0; k0 < ND; k0 += 16) {
        // commit prefetched tile to smem (transposed k-major)
        As[akc + 0][ar0] = pa0.x; As[akc + 1][ar0] = pa0.y;
        As[akc + 2][ar0] = pa0.z; As[akc + 3][ar0] = pa0.w;
        As[akc + 0][ar1] = pa1.x; As[akc + 1][ar1] = pa1.y;
        As[akc + 2][ar1] = pa1.z; As[akc + 3][ar1] = pa1.w;
        Bs[akc + 0][ar0] = pb0.x; Bs[akc + 1][ar0] = pb0.y;
        Bs[akc + 2][ar0] = pb0.z; Bs[akc + 3][ar0] = pb0.w;
        Bs[akc + 0][ar1] = pb1.x; Bs[akc + 1][ar1] = pb1.y;
        Bs[akc + 2][ar1] = pb1.z; Bs[akc + 3][ar1] = pb1.w;
        __syncthreads();

        if (k0 + 16 < ND) {  // issue next tile's loads; land during compute
            const float* An = Ab + (k0 + 16 + akc);
            pa0 = *(const float4*)(An + (size_t)ar0 * ND);
            pa1 = *(const float4*)(An + (size_t)ar1 * ND);
            const float* Wn = Wb + (k0 + 16 + akc);
            pb0 = *(const float4*)(Wn + (size_t)ar0 * ND);
            pb1 = *(const float4*)(Wn + (size_t)ar1 * ND);
        }

        #pragma unroll 4
        for (int kk = 0; kk < 16; ++kk) {
            float4 a0v = *(const float4*)&As[kk][ri * 8];
            float4 a1v = *(const float4*)&As[kk][ri * 8 + 4];
            ulonglong2 b01 = *(const ulonglong2*)&Bs[kk][ci * 8];
            ulonglong2 b23 = *(const ulonglong2*)&Bs[kk][ci * 8 + 4];
            u64 bb[4] = {b01.x, b01.y, b23.x, b23.y};
            float af[8] = {a0v.x, a0v.y, a0v.z, a0v.w,
                           a1v.x, a1v.y, a1v.z, a1v.w};
            #pragma unroll
            for (int i = 0; i < 8; ++i) {
                u64 ad = pk2(af[i], af[i]);
                #pragma unroll
                for (int j = 0; j < 4; ++j)
                    fma2(acc[i][j], ad, bb[j]);
            }
        }
        __syncthreads();
    }

    if (!QKV || mode >= 2) {
        // natural [m][n] store
        #pragma unroll
        for (int i = 0; i < 8; ++i) {
            float r[8];
            #pragma unroll
            for (int j = 0; j < 4; ++j) upk2(acc[i][j], r[2 * j], r[2 * j + 1]);
            size_t m = (size_t)(bm0 + ri * 8 + i);
            float* cp = C + m * ND + bn0 + ci * 8;
            *(float4*)cp       = make_float4(r[0], r[1], r[2], r[3]);
            *(float4*)(cp + 4) = make_float4(r[4], r[5], r[6], r[7]);
        }
    } else {
        // fused RoPE + transposed store: addr = b*2^21 + n*2048 + t
        const int nbase = bn0 + ci * 8;             // 8 consecutive n = 4 RoPE pairs
        const int ip0   = (nbase & 63) >> 1;        // pair index within head
        #pragma unroll
        for (int i = 0; i < 8; ++i) {
            float r[8];
            #pragma unroll
            for (int j = 0; j < 4; ++j) upk2(acc[i][j], r[2 * j], r[2 * j + 1]);
            int m  = bm0 + ri * 8 + i;
            int bb = m >> 11;
            int t  = m & (NT - 1);
            const float4* rp = (const float4*)&g_rope[t * 64 + ip0 * 2];
            float4 r01 = rp[0];
            float4 r23 = rp[1];
            float* cb = C + (size_t)bb * (ND * NT) + t;
            cb[(size_t)(nbase + 0) * NT] = r[0] * r01.x - r[1] * r01.y;
            cb[(size_t)(nbase + 1) * NT] = r[0] * r01.y + r[1] * r01.x;
            cb[(size_t)(nbase + 2) * NT] = r[2] * r01.z - r[3] * r01.w;
            cb[(size_t)(nbase + 3) * NT] = r[2] * r01.w + r[3] * r01.z;
            cb[(size_t)(nbase + 4) * NT] = r[4] * r23.x - r[5] * r23.y;
            cb[(size_t)(nbase + 5) * NT] = r[4] * r23.y + r[5] * r23.x;
            cb[(size_t)(nbase + 6) * NT] = r[6] * r23.z - r[7] * r23.w;
            cb[(size_t)(nbase + 7) * NT] = r[6] * r23.w + r[7] * r23.z;
        }
    }
}

// Fused Q/K/V projection: blockIdx.z selects weight + epilogue mode.
__global__ __launch_bounds__(256, 2)
void gemm_qkv_kernel(const float* __restrict__ x,
                     const float* __restrict__ wq,
                     const float* __restrict__ wk,
                     const float* __restrict__ wv)
{
    const int mode = blockIdx.z;                    // 0=Q, 1=K, 2=V
    const float* W = (mode == 0) ? wq : (mode == 1) ? wk : wv;
    float* C = (mode == 0) ? g_qT : (mode == 1) ? g_kT : g_v;
    gemm128_body<true>(x, W, C, mode);
}

// Output projection: A = g_xo, C = harness output buffer.
__global__ __launch_bounds__(256, 2)
void gemm_out_kernel(const float* __restrict__ wo, float* __restrict__ out)
{
    gemm128_body<false>(g_xo, wo, out, 3);
}

// ---------------------------------------------------------------------------
// Causal flash attention, S-tile = 128(q) x 64(k), head_dim 64.
// grid = (16 q-tiles, 32 (b,h)), 256 threads; thread tile 8 rows x 4 cols.
// R = tid>>4 owns rows qb+R*8..+8; Cc = tid&15 owns cols kb+Cc*4..+4; the
// 16-lane Cc group spans a full row -> shfl-xor row reductions unchanged.
// Row-pair packed f32x2 accumulators: (r,r+1) x dup(b). Q/K read d-major.
// P^T staged through the K smem buffer (stride 132) for the PV pass.
// Dynamic smem 82944 B -> 2 blocks/SM. Heavy q-tiles launch first.
// ---------------------------------------------------------------------------
__global__ __launch_bounds__(256, 2)
void attn_kernel()
{
    extern __shared__ __align__(16) float smf[];
    float* Qt = smf;                    // [64 d][128 r]  stride 128
    float* KP = smf + 64 * 128;         // K: [64 d][c] / P^T: [64 c][r], stride 132
    float* Vs = KP + 64 * 132;          // [64 c][64 dd]

    const int tid = threadIdx.x;
    const int Cc  = tid & 15;
    const int R   = tid >> 4;
    const int qt  = 15 - blockIdx.x;    // heavy tiles first
    const int bh  = blockIdx.y;         // 0..31
    const int b   = bh >> 4;
    const int h   = bh & 15;
    const int qb  = qt * 128;

    const size_t tbase = (size_t)b * (ND * NT) + (size_t)(h * 64) * NT;  // + d*NT + t
    const size_t vbase = (size_t)(b * NT) * ND + h * 64;

    // load Q tile [64 d][128 r] (d-major, coalesced along t)
    #pragma unroll
    for (int u = 0; u < 8; ++u) {
        int fi = tid + (u << 8);
        int d  = fi >> 5;
        int r4 = (fi & 31) << 2;
        *(float4*)&Qt[d * 128 + r4] =
            *(const float4*)&g_qT[tbase + (size_t)d * NT + qb + r4];
    }

    float m_i[8], l_i[8];
    u64   o[4][4];                      // [row-pair][col]
    #pragma unroll
    for (int i = 0; i < 8; ++i) { m_i[i] = -3.0e38f; l_i[i] = 0.0f; }
    #pragma unroll
    for (int ip = 0; ip < 4; ++ip)
        #pragma unroll
        for (int j = 0; j < 4; ++j) o[ip][j] = 0ULL;

    const int nkt = 2 * qt + 2;
    for (int kt = 0; kt < nkt; ++kt) {
        const int kb = kt * 64;
        __syncthreads();  // prev PV done reading KP/Vs (and Q visible on kt=0)
        #pragma unroll
        for (int u = 0; u < 4; ++u) {
            int fi = tid + (u << 8);
            int r  = fi >> 4;
            int c4 = (fi & 15) << 2;
            *(float4*)&KP[r * 132 + c4] =
                *(const float4*)&g_kT[tbase + (size_t)r * NT + kb + c4];
            *(float4*)&Vs[r * 64 + c4] =
                *(const float4*)&g_v[vbase + (size_t)(kb + r) * ND + c4];
        }
        __syncthreads();

        // S = Q . K^T  (row-pair packed; raw scores, 1/8 applied inside exp)
        u64 sp[4][4];
        #pragma unroll
        for (int ip = 0; ip < 4; ++ip)
            #pragma unroll
            for (int j = 0; j < 4; ++j) sp[ip][j] = 0ULL;

        #pragma unroll 4
        for (int d = 0; d < 64; ++d) {
            ulonglong2 qa = *(const ulonglong2*)&Qt[d * 128 + R * 8];
            ulonglong2 qc = *(const ulonglong2*)&Qt[d * 128 + R * 8 + 4];
            float4 kv = *(const float4*)&KP[d * 132 + Cc * 4];
            u64 ap[4] = {qa.x, qa.y, qc.x, qc.y};      // (r0,r1)(r2,r3)(r4,r5)(r6,r7)
            u64 bd[4] = {pk2(kv.x, kv.x), pk2(kv.y, kv.y),
                         pk2(kv.z, kv.z), pk2(kv.w, kv.w)};
            #pragma unroll
            for (int ip = 0; ip < 4; ++ip)
                #pragma unroll
                for (int j = 0; j < 4; ++j)
                    fma2(sp[ip][j], ap[ip], bd[j]);
        }

        float s[8][4];
        #pragma unroll
        for (int ip = 0; ip < 4; ++ip)
            #pragma unroll
            for (int j = 0; j < 4; ++j)
                upk2(sp[ip][j], s[2 * ip][j], s[2 * ip + 1][j]);

        if (kb + 64 > qb) {  // partial tile: causal mask on global indices
            #pragma unroll
            for (int i = 0; i < 8; ++i)
                #pragma unroll
                for (int j = 0; j < 4; ++j)
                    if (kb + Cc * 4 + j > qb + R * 8 + i) s[i][j] = -1.0e30f;
        }

        // online softmax update (row spans the 16-lane Cc group)
        float al[8];
        #pragma unroll
        for (int i = 0; i < 8; ++i) {
            float mx = fmaxf(fmaxf(s[i][0], s[i][1]), fmaxf(s[i][2], s[i][3]));
            mx = fmaxf(mx, __shfl_xor_sync(0xffffffffu, mx, 1));
            mx = fmaxf(mx, __shfl_xor_sync(0xffffffffu, mx, 2));
            mx = fmaxf(mx, __shfl_xor_sync(0xffffffffu, mx, 4));
            mx = fmaxf(mx, __shfl_xor_sync(0xffffffffu, mx, 8));
            float mn = fmaxf(m_i[i], mx);
            al[i] = __expf((m_i[i] - mn) * 0.125f);
            m_i[i] = mn;
            float ps = 0.0f;
            #pragma unroll
            for (int j = 0; j < 4; ++j) {
                s[i][j] = __expf((s[i][j] - mn) * 0.125f);
                ps += s[i][j];
            }
            ps += __shfl_xor_sync(0xffffffffu, ps, 1);
            ps += __shfl_xor_sync(0xffffffffu, ps, 2);
            ps += __shfl_xor_sync(0xffffffffu, ps, 4);
            ps += __shfl_xor_sync(0xffffffffu, ps, 8);
            l_i[i] = l_i[i] * al[i] + ps;
        }
        #pragma unroll
        for (int ip = 0; ip < 4; ++ip) {
            u64 alp = pk2(al[2 * ip], al[2 * ip + 1]);
            #pragma unroll
            for (int j = 0; j < 4; ++j) mul2(o[ip][j], alp);
        }

        __syncthreads();  // all S reads of KP done
        // write P^T[c][r] (each thread owns 8 consecutive r for its 4 cols)
        #pragma unroll
        for (int j = 0; j < 4; ++j) {
            float* pt = &KP[(Cc * 4 + j) * 132 + R * 8];
            *(float4*)pt       = make_float4(s[0][j], s[1][j], s[2][j], s[3][j]);
            *(float4*)(pt + 4) = make_float4(s[4][j], s[5][j], s[6][j], s[7][j]);
        }
        __syncthreads();

        // O += P . V (row-pair packed)
        #pragma unroll 4
        for (int c = 0; c < 64; ++c) {
            ulonglong2 pa = *(const ulonglong2*)&KP[c * 132 + R * 8];
            ulonglong2 pc = *(const ulonglong2*)&KP[c * 132 + R * 8 + 4];
            float4 vv = *(const float4*)&Vs[c * 64 + Cc * 4];
            u64 ap[4] = {pa.x, pa.y, pc.x, pc.y};
            u64 bd[4] = {pk2(vv.x, vv.x), pk2(vv.y, vv.y),
                         pk2(vv.z, vv.z), pk2(vv.w, vv.w)};
            #pragma unroll
            for (int ip = 0; ip < 4; ++ip)
                #pragma unroll
                for (int j = 0; j < 4; ++j)
                    fma2(o[ip][j], ap[ip], bd[j]);
        }
    }

    // normalize and store (natural layout for final projection)
    #pragma unroll
    for (int ip = 0; ip < 4; ++ip) {
        float lo[4], hi[4];
        #pragma unroll
        for (int j = 0; j < 4; ++j) upk2(o[ip][j], lo[j], hi[j]);
        float inv0 = 1.0f / l_i[2 * ip];
        float inv1 = 1.0f / l_i[2 * ip + 1];
        int t0 = qb + R * 8 + 2 * ip;
        *(float4*)&g_xo[(size_t)(b * NT + t0) * ND + h * 64 + Cc * 4] =
            make_float4(lo[0] * inv0, lo[1] * inv0, lo[2] * inv0, lo[3] * inv0);
        *(float4*)&g_xo[(size_t)(b * NT + t0 + 1) * ND + h * 64 + Cc * 4] =
            make_float4(hi[0] * inv1, hi[1] * inv1, hi[2] * inv1, hi[3] * inv1);
    }
}

// ---------------------------------------------------------------------------
extern "C" void kernel_launch(void* const* d_in, const int* in_sizes, int n_in,
                              void* d_out, int out_size)
{
    const float* x  = (const float*)d_in[0];
    const float* wq = (const float*)d_in[1];
    const float* wk = (const float*)d_in[2];
    const float* wv = (const float*)d_in[3];
    const float* wo = (const float*)d_in[4];
    float* out = (float*)d_out;

    const int attn_smem = (64 * 128 + 64 * 132 + 64 * 64) * 4;  // 82944 B
    cudaFuncSetAttribute(attn_kernel,
                         cudaFuncAttributeMaxDynamicSharedMemorySize, attn_smem);

    rope_fill_kernel<<<(NT * 32 + 255) / 256, 256>>>();

    dim3 gqkv(ND / 128, NM / 128, 3);                 // (8, 32, 3)
    gemm_qkv_kernel<<<gqkv, 256>>>(x, wq, wk, wv);    // Q/K/V proj (+RoPE on Q/K)

    attn_kernel<<<dim3(16, 32), 256, attn_smem>>>();  // causal flash attention

    dim3 go(ND / 128, NM / 128);                      // (8, 32)
    gemm_out_kernel<<<go, 256>>>(wo, out);            // output projection
}